// round 13
// baseline (speedup 1.0000x reference)
#include <cuda_runtime.h>

#define BS    64
#define SL    8192
#define EDIM  64
#define DDIM  64
#define VOCAB 1088
#define NVAL  64
#define NTILE 17
#define SPLIT 8
#define CHUNK (SL / SPLIT)          // 1024
#define EPT   4
#define NPROD BS                    // producer blocks (one per batch)
#define EKGRID (NPROD + BS * NTILE) // 64 + 1088 = 1152

// Scratch (no allocations allowed)
__device__ float g_Qk[BS * EDIM];
__device__ float g_EV[BS * NVAL];
__device__ float g_EK[BS * VOCAB];
__device__ float g_num[BS * NVAL];      // zero-init; reset by combining block
__device__ int   g_cnt[BS];             // zero-init; reset by combining block
__device__ volatile int g_qkflag[BS];   // producer->consumer flag (self-reset)
__device__ int   g_done[BS];            // consumer count (self-reset)

// ---------------------------------------------------------------------------
// A: fused table kernel. grid = 64 producers + 64x17 consumers, 128 threads.
// Producers (bid<64): q -> eq -> Q -> one coalesced Wk pass -> Qk + EV, flag.
// Consumers: embK tile load in flight, spin on flag, dot, exp, write EK.
// All 1152 blocks co-resident (128 thr, ~17.3KB smem) => spin is safe.
// ---------------------------------------------------------------------------
__global__ __launch_bounds__(128) void ek_fused_kernel(
    const int*   __restrict__ q,
    const float* __restrict__ embK,
    const float* __restrict__ Wk_w,   // (64, 128) row-major
    const float* __restrict__ Wq_w,   // (64, 64) row-major
    const float* __restrict__ Wq_b)
{
    const int bid = blockIdx.x;
    const int tid = threadIdx.x;

    __shared__ float tl[64 * 65];     // consumer tile (padded); unused by prod
    __shared__ float qks[EDIM];
    __shared__ float part[128];
    __shared__ float Qs[DDIM];

    if (bid < NPROD) {
        // ---------------- Producer: batch b = bid ----------------
        const int b = bid;
        // eq row (tid<64)
        if (tid < EDIM) part[tid] = embK[(size_t)q[b] * EDIM + tid]; // stash eq in part[0..63]
        __syncthreads();
        float eq_lo[2];               // not needed; read from shared below

        // Q: thread (d = tid>>1, h = tid&1) -> 32-wide partial via f4 row loads
        {
            const int d = tid >> 1, h = tid & 1;
            const float4* wrow = reinterpret_cast<const float4*>(
                Wq_w + (size_t)d * EDIM + h * 32);
            float acc = 0.f;
            #pragma unroll
            for (int i = 0; i < 8; i++) {
                const float4 w4 = wrow[i];
                const int e = h * 32 + i * 4;
                acc += w4.x * part[e] + w4.y * part[e + 1]
                     + w4.z * part[e + 2] + w4.w * part[e + 3];
            }
            qks[0] = qks[0];          // no-op; keep compiler quiet
            Qs[d] = 0.f;              // init once per pair is fine (both write same later)
            // store partial in upper half of tl scratch (avoid part[] in use)
            tl[tid] = acc;
        }
        __syncthreads();
        if (tid < DDIM)
            Qs[tid] = tl[tid * 2] + tl[tid * 2 + 1] + Wq_b[tid];
        __syncthreads();

        // One coalesced pass over ALL 128 Wk columns: c = tid
        {
            const int c = tid;
            float acc = 0.f;
            #pragma unroll
            for (int d = 0; d < DDIM; d++)
                acc = fmaf(Wk_w[(size_t)d * 128 + c], Qs[d], acc);
            acc *= 0.125f;
            if (c < NVAL) g_EV[b * NVAL + c] = __expf(acc);
            else          g_Qk[b * EDIM + (c - NVAL)] = acc;
        }
        __threadfence();
        __syncthreads();
        if (tid == 0) g_qkflag[b] = 1;
    } else {
        // ---------------- Consumer: tile of a batch ----------------
        const int cid  = bid - NPROD;
        const int b    = cid / NTILE;
        const int tile = cid % NTILE;
        const int v0   = tile * 64;
        const int v    = tid & 63;
        const int h    = tid >> 6;

        // Tile load first — in flight during the spin below
        {
            const float4* src = reinterpret_cast<const float4*>(embK + (size_t)v0 * EDIM);
            for (int i = tid; i < 1024; i += 128) {
                const float4 val = src[i];
                float* d = &tl[(i >> 4) * 65 + (i & 15) * 4];
                d[0] = val.x; d[1] = val.y; d[2] = val.z; d[3] = val.w;
            }
        }

        if (tid == 0) {
            while (g_qkflag[b] == 0) __nanosleep(32);
            __threadfence();          // acquire
        }
        __syncthreads();
        if (tid < EDIM) qks[tid] = g_Qk[b * EDIM + tid];
        __syncthreads();

        float acc = 0.f;
        #pragma unroll
        for (int i = 0; i < 32; i++)
            acc = fmaf(tl[v * 65 + h * 32 + i], qks[h * 32 + i], acc);
        part[tid] = acc;
        __syncthreads();

        if (tid < 64)
            g_EK[(size_t)b * VOCAB + v0 + tid] = __expf(part[tid] + part[tid + 64]);
        __syncthreads();

        // Last-of-17 consumers re-arms the per-batch flag for graph replay
        if (tid == 0) {
            const int old = atomicAdd(&g_done[b], 1);
            if (old == NTILE - 1) { g_done[b] = 0; g_qkflag[b] = 0; }
        }
    }
}

// ---------------------------------------------------------------------------
// Kernel B: gather-histogram (byte-identical to R11: measured best).
// grid = 64 batches x 8 splits (512 blocks), 256 threads, 4 elems/thread.
// ---------------------------------------------------------------------------
__global__ __launch_bounds__(256) void attn_kernel(
    const int* __restrict__ x,
    float*     __restrict__ out)
{
    const int b    = blockIdx.x >> 3;
    const int sp   = blockIdx.x & 7;
    const int tid  = threadIdx.x;
    const int warp = tid >> 5;

    __shared__ float EKs[VOCAB];
    __shared__ float bins[8][NVAL];
    __shared__ float num[NVAL];
    __shared__ float rcpZ;
    __shared__ int   lastFlag;

    const int* kp = x + (size_t)b * 2 * SL + sp * CHUNK;
    const int* vp = kp + SL;
    const int4 k4 = __ldg(reinterpret_cast<const int4*>(kp) + tid);
    const int4 w4 = __ldg(reinterpret_cast<const int4*>(vp) + tid);

    {
        const float4* src = reinterpret_cast<const float4*>(g_EK + (size_t)b * VOCAB);
        float4* dst = reinterpret_cast<float4*>(EKs);
        for (int i = tid; i < VOCAB / 4; i += 256) dst[i] = src[i];
    }
    for (int i = tid; i < 8 * NVAL; i += 256) (&bins[0][0])[i] = 0.f;
    __syncthreads();

    const int kk[EPT] = {k4.x, k4.y, k4.z, k4.w};
    const int vv[EPT] = {w4.x - NVAL, w4.y - NVAL, w4.z - NVAL, w4.w - NVAL};

    #pragma unroll
    for (int i = 0; i < EPT; i++)
        atomicAdd(&bins[warp][vv[i]], EKs[kk[i]]);
    __syncthreads();

    if (tid < NVAL) {
        float bsum = 0.f;
        #pragma unroll
        for (int w = 0; w < 8; w++) bsum += bins[w][tid];
        atomicAdd(&g_num[b * NVAL + tid], bsum);
    }
    __syncthreads();

    if (tid == 0) {
        __threadfence();
        const int old = atomicAdd(&g_cnt[b], 1);
        lastFlag = (old == SPLIT - 1) ? 1 : 0;
        __threadfence();
    }
    __syncthreads();

    if (lastFlag) {
        if (tid < NVAL) {
            volatile float* vnum = g_num + b * NVAL;
            num[tid] = vnum[tid] * g_EV[b * NVAL + tid];
        }
        __syncthreads();
        if (tid < 32) {
            float zz = num[tid] + num[tid + 32];
            #pragma unroll
            for (int o = 16; o > 0; o >>= 1) zz += __shfl_xor_sync(0xffffffffu, zz, o);
            if (tid == 0) rcpZ = __frcp_rn(zz);
        }
        __syncthreads();
        if (tid < NVAL) {
            out[b * NVAL + tid] = num[tid] * rcpZ;
            g_num[b * NVAL + tid] = 0.f;
        }
        __syncthreads();
        if (tid == 0) g_cnt[b] = 0;
    }
}

// ---------------------------------------------------------------------------
// Inputs (metadata order): x(int32), q(int32), embK, Wk_w, Wk_b, Wq_w, Wq_b.
// Wk_b is softmax-invariant (constant per batch) and intentionally unused.
// ---------------------------------------------------------------------------
extern "C" void kernel_launch(void* const* d_in, const int* in_sizes, int n_in,
                              void* d_out, int out_size)
{
    const int*   x    = (const int*)  d_in[0];
    const int*   q    = (const int*)  d_in[1];
    const float* embK = (const float*)d_in[2];
    const float* Wk_w = (const float*)d_in[3];
    const float* Wq_w = (const float*)d_in[5];
    const float* Wq_b = (const float*)d_in[6];
    float* out = (float*)d_out;

    ek_fused_kernel<<<EKGRID, 128>>>(q, embK, Wk_w, Wq_w, Wq_b);
    attn_kernel<<<BS * SPLIT, 256>>>(x, out);
}

// round 14
// speedup vs baseline: 1.3828x; 1.3828x over previous
#include <cuda_runtime.h>

#define BS    64
#define SL    8192
#define EDIM  64
#define DDIM  64
#define VOCAB 1088
#define NVAL  64
#define NTILE 17
#define SPLIT 8
#define CHUNK (SL / SPLIT)          // 1024
#define EPT   4

// Scratch (no allocations allowed)
__device__ float g_Qk[BS * EDIM];
__device__ float g_EV[BS * NVAL];
__device__ float g_EK[BS * VOCAB];
__device__ float g_num[BS * NVAL];   // zero-init; reset by combining block
__device__ int   g_cnt[BS];          // zero-init; reset by combining block

// ---------------------------------------------------------------------------
// A1: Q, Qk, EV per batch. 64 blocks x 256 threads.
// ALL weight operands (Wq, Wk, Wq_b) are prefetched into REGISTERS at entry,
// before the dependent q -> embK chain resolves. The critical path is then:
//   LDG q -> LDG eq -> FMA(Q)+reduce -> FMA(Qk)+reduce -> exp -> STG
// ---------------------------------------------------------------------------
__global__ __launch_bounds__(256) void qk_kernel(
    const int*   __restrict__ q,
    const float* __restrict__ embK,
    const float* __restrict__ Wk_w,   // (64, 128) row-major
    const float* __restrict__ Wq_w,   // (64, 64) row-major
    const float* __restrict__ Wq_b)
{
    const int b   = blockIdx.x;
    const int tid = threadIdx.x;

    __shared__ float eqs[EDIM];
    __shared__ float Qs [DDIM];
    __shared__ float part[256];

    // ---- Start the dependent chain immediately ----
    const int qi = q[b];                       // LDG (broadcast)

    // ---- Prefetch (independent of the chain): Wq segment ----
    const int d_q = tid >> 2, s_q = tid & 3;   // Q layout: thread = (row d, 16-seg s)
    float4 wq[4];
    {
        const float4* wrow = reinterpret_cast<const float4*>(
            Wq_w + (size_t)d_q * EDIM + s_q * 16);
        #pragma unroll
        for (int i = 0; i < 4; i++) wq[i] = wrow[i];
    }
    // ---- Prefetch: Wk column half (coalesced across lanes) ----
    const int c  = tid & 127, hh = tid >> 7;   // Qk layout: thread = (col c, d-half hh)
    float wk[32];
    {
        const float* base = Wk_w + (size_t)hh * 32 * 128 + c;
        #pragma unroll
        for (int i = 0; i < 32; i++) wk[i] = base[(size_t)i * 128];
    }
    const float wqb = (tid < DDIM) ? Wq_b[tid] : 0.f;

    // ---- eq row (depends on qi) ----
    if (tid < EDIM) eqs[tid] = embK[(size_t)qi * EDIM + tid];
    __syncthreads();

    // ---- Q: 16-wide partial on prefetched wq ----
    {
        float acc = 0.f;
        #pragma unroll
        for (int i = 0; i < 4; i++) {
            const int e = s_q * 16 + i * 4;
            acc += wq[i].x * eqs[e]     + wq[i].y * eqs[e + 1]
                 + wq[i].z * eqs[e + 2] + wq[i].w * eqs[e + 3];
        }
        part[tid] = acc;
    }
    __syncthreads();
    if (tid < DDIM)
        Qs[tid] = part[tid * 4] + part[tid * 4 + 1]
                + part[tid * 4 + 2] + part[tid * 4 + 3] + wqb;
    __syncthreads();

    // ---- Qk/SV: 32-d partial on prefetched wk ----
    {
        float acc = 0.f;
        #pragma unroll
        for (int i = 0; i < 32; i++)
            acc = fmaf(wk[i], Qs[hh * 32 + i], acc);
        part[tid] = acc;
    }
    __syncthreads();
    if (tid < 128) {
        const float val = (part[tid] + part[tid + 128]) * 0.125f;
        if (tid < NVAL) g_EV[b * NVAL + tid] = __expf(val);      // cols 0..63 = SV
        else            g_Qk[b * EDIM + (tid - NVAL)] = val;     // cols 64..127 = Qk
    }
}

// ---------------------------------------------------------------------------
// A2: EK. grid = 64 batches x 17 tiles = 1088 independent blocks, 128 threads.
// (Byte-identical to R11 — measured fast.)
// ---------------------------------------------------------------------------
__global__ __launch_bounds__(128) void ek_kernel(const float* __restrict__ embK)
{
    const int bid  = blockIdx.x;
    const int b    = bid / NTILE;
    const int tile = bid % NTILE;
    const int v0   = tile * 64;
    const int tid  = threadIdx.x;
    const int v    = tid & 63;
    const int h    = tid >> 6;

    __shared__ float qks[EDIM];
    __shared__ float tl[64 * 65];
    __shared__ float part[128];

    if (tid < EDIM) qks[tid] = g_Qk[b * EDIM + tid];
    {
        const float4* src = reinterpret_cast<const float4*>(embK + (size_t)v0 * EDIM);
        for (int i = tid; i < 1024; i += 128) {
            const float4 val = src[i];
            float* d = &tl[(i >> 4) * 65 + (i & 15) * 4];
            d[0] = val.x; d[1] = val.y; d[2] = val.z; d[3] = val.w;
        }
    }
    __syncthreads();

    float acc = 0.f;
    #pragma unroll
    for (int i = 0; i < 32; i++)
        acc = fmaf(tl[v * 65 + h * 32 + i], qks[h * 32 + i], acc);
    part[tid] = acc;
    __syncthreads();

    if (tid < 64)
        g_EK[(size_t)b * VOCAB + v0 + tid] = __expf(part[tid] + part[tid + 64]);
}

// ---------------------------------------------------------------------------
// Kernel B: gather-histogram (byte-identical to R11: measured best).
// grid = 64 batches x 8 splits (512 blocks), 256 threads, 4 elems/thread.
// ---------------------------------------------------------------------------
__global__ __launch_bounds__(256) void attn_kernel(
    const int* __restrict__ x,
    float*     __restrict__ out)
{
    const int b    = blockIdx.x >> 3;
    const int sp   = blockIdx.x & 7;
    const int tid  = threadIdx.x;
    const int warp = tid >> 5;

    __shared__ float EKs[VOCAB];
    __shared__ float bins[8][NVAL];
    __shared__ float num[NVAL];
    __shared__ float rcpZ;
    __shared__ int   lastFlag;

    const int* kp = x + (size_t)b * 2 * SL + sp * CHUNK;
    const int* vp = kp + SL;
    const int4 k4 = __ldg(reinterpret_cast<const int4*>(kp) + tid);
    const int4 w4 = __ldg(reinterpret_cast<const int4*>(vp) + tid);

    {
        const float4* src = reinterpret_cast<const float4*>(g_EK + (size_t)b * VOCAB);
        float4* dst = reinterpret_cast<float4*>(EKs);
        for (int i = tid; i < VOCAB / 4; i += 256) dst[i] = src[i];
    }
    for (int i = tid; i < 8 * NVAL; i += 256) (&bins[0][0])[i] = 0.f;
    __syncthreads();

    const int kk[EPT] = {k4.x, k4.y, k4.z, k4.w};
    const int vv[EPT] = {w4.x - NVAL, w4.y - NVAL, w4.z - NVAL, w4.w - NVAL};

    #pragma unroll
    for (int i = 0; i < EPT; i++)
        atomicAdd(&bins[warp][vv[i]], EKs[kk[i]]);
    __syncthreads();

    if (tid < NVAL) {
        float bsum = 0.f;
        #pragma unroll
        for (int w = 0; w < 8; w++) bsum += bins[w][tid];
        atomicAdd(&g_num[b * NVAL + tid], bsum);
    }
    __syncthreads();

    if (tid == 0) {
        __threadfence();
        const int old = atomicAdd(&g_cnt[b], 1);
        lastFlag = (old == SPLIT - 1) ? 1 : 0;
        __threadfence();
    }
    __syncthreads();

    if (lastFlag) {
        if (tid < NVAL) {
            volatile float* vnum = g_num + b * NVAL;
            num[tid] = vnum[tid] * g_EV[b * NVAL + tid];
        }
        __syncthreads();
        if (tid < 32) {
            float zz = num[tid] + num[tid + 32];
            #pragma unroll
            for (int o = 16; o > 0; o >>= 1) zz += __shfl_xor_sync(0xffffffffu, zz, o);
            if (tid == 0) rcpZ = __frcp_rn(zz);
        }
        __syncthreads();
        if (tid < NVAL) {
            out[b * NVAL + tid] = num[tid] * rcpZ;
            g_num[b * NVAL + tid] = 0.f;
        }
        __syncthreads();
        if (tid == 0) g_cnt[b] = 0;
    }
}

// ---------------------------------------------------------------------------
// Inputs (metadata order): x(int32), q(int32), embK, Wk_w, Wk_b, Wq_w, Wq_b.
// Wk_b is softmax-invariant (constant per batch) and intentionally unused.
// ---------------------------------------------------------------------------
extern "C" void kernel_launch(void* const* d_in, const int* in_sizes, int n_in,
                              void* d_out, int out_size)
{
    const int*   x    = (const int*)  d_in[0];
    const int*   q    = (const int*)  d_in[1];
    const float* embK = (const float*)d_in[2];
    const float* Wk_w = (const float*)d_in[3];
    const float* Wq_w = (const float*)d_in[5];
    const float* Wq_b = (const float*)d_in[6];
    float* out = (float*)d_out;

    qk_kernel<<<BS, 256>>>(q, embK, Wk_w, Wq_w, Wq_b);
    ek_kernel<<<BS * NTILE, 128>>>(embK);
    attn_kernel<<<BS * SPLIT, 256>>>(x, out);
}